// round 9
// baseline (speedup 1.0000x reference)
#include <cuda_runtime.h>
#include <cuda_bf16.h>
#include <math.h>
#include <stdint.h>

#define NL 12
#define NH 16
#define NC 1024
#define NT 512
#define NB 4
#define HDIM 64
#define NF 4096
#define NV 32000
#define MROWS (NB*NT)   // 2048
#define C3 (3*NC)       // 3072
#define LN_EPS 1e-5f

typedef __nv_bfloat16 bf16;
typedef __nv_bfloat162 bf162;

// ---------------- static scratch ----------------
__device__ float g_x   [MROWS*NC];
__device__ float g_qkv [MROWS*C3];
__device__ bf16  g_xn_h[MROWS*NC];
__device__ bf16  g_xn_l[MROWS*NC];
__device__ bf16  g_y_h [MROWS*NC];
__device__ bf16  g_y_l [MROWS*NC];
__device__ bf16  g_h_h [MROWS*NF];
__device__ bf16  g_h_l [MROWS*NF];

// split weights, K-major W[K,N] (as in reference)
__device__ bf16 g_wqkv_h[(long)NL*NC*C3];
__device__ bf16 g_wqkv_l[(long)NL*NC*C3];
__device__ bf16 g_wo_h  [(long)NL*NC*NC];
__device__ bf16 g_wo_l  [(long)NL*NC*NC];
__device__ bf16 g_w1_h  [(long)NL*NC*NF];
__device__ bf16 g_w1_l  [(long)NL*NC*NF];
__device__ bf16 g_w2_h  [(long)NL*NF*NC];
__device__ bf16 g_w2_l  [(long)NL*NF*NC];
__device__ bf16 g_lm_h  [(long)NC*NV];
__device__ bf16 g_lm_l  [(long)NC*NV];

__device__ __forceinline__ void split2(float v, bf16& h, bf16& l) {
    h = __float2bfloat16(v);
    l = __float2bfloat16(v - __bfloat162float(h));
}

// ---------------- conversion kernels ----------------
// 4 independent splits fused into one launch
__global__ void split4_kernel(const float* __restrict__ i0, bf16* __restrict__ h0, bf16* __restrict__ l0, long n0,
                              const float* __restrict__ i1, bf16* __restrict__ h1, bf16* __restrict__ l1, long n1,
                              const float* __restrict__ i2, bf16* __restrict__ h2, bf16* __restrict__ l2, long n2,
                              const float* __restrict__ i3, bf16* __restrict__ h3, bf16* __restrict__ l3, long n3) {
    long total = n0 + n1 + n2 + n3;
    for (long i = (long)blockIdx.x * blockDim.x + threadIdx.x; i < total;
         i += (long)gridDim.x * blockDim.x) {
        const float* in; bf16 *oh, *ol; long j = i;
        if (j < n0)                { in = i0; oh = h0; ol = l0; }
        else if ((j -= n0) < n1)   { in = i1; oh = h1; ol = l1; }
        else if ((j -= n1) < n2)   { in = i2; oh = h2; ol = l2; }
        else { j -= n2;              in = i3; oh = h3; ol = l3; }
        float v = in[j];
        bf16 h, l; split2(v, h, l);
        oh[j] = h; ol[j] = l;
    }
}

__global__ void pack_qkv_kernel(const float* __restrict__ wq,
                                const float* __restrict__ wk,
                                const float* __restrict__ wv,
                                bf16* __restrict__ oh, bf16* __restrict__ ol, long n) {
    for (long i = (long)blockIdx.x * blockDim.x + threadIdx.x; i < n;
         i += (long)gridDim.x * blockDim.x) {
        long lk = i / C3;        // l*NC + k
        int  j  = (int)(i % C3);
        int sel = j >> 10, jj = j & 1023;
        const float* src = (sel == 0) ? wq : (sel == 1) ? wk : wv;
        float v = src[lk * NC + jj];
        bf16 h, l; split2(v, h, l);
        oh[i] = h; ol[i] = l;
    }
}

// ---------------- embedding ----------------
__global__ void embed_kernel(const int* __restrict__ idx,
                             const float* __restrict__ tok,
                             const float* __restrict__ pos) {
    int row = blockIdx.x, t = row % NT;
    int tk = idx[row];
    const float4* tr = (const float4*)(tok + (long)tk * NC);
    const float4* pr = (const float4*)(pos + (long)t  * NC);
    float4* xr = (float4*)(g_x + (long)row * NC);
    for (int c = threadIdx.x; c < NC / 4; c += blockDim.x) {
        float4 a = tr[c], b = pr[c];
        a.x += b.x; a.y += b.y; a.z += b.z; a.w += b.w;
        xr[c] = a;
    }
}

// ---------------- layernorm + split (256 thr/row) ----------------
__global__ __launch_bounds__(256)
void ln_split_kernel(const float* __restrict__ x,
                     const float* __restrict__ gg,
                     const float* __restrict__ bb,
                     bf16* __restrict__ oh, bf16* __restrict__ ol) {
    __shared__ float rs[8], rs2[8];
    const int row = blockIdx.x, tid = threadIdx.x;
    const float4* xr = (const float4*)(x + (long)row * NC);
    float4 v = xr[tid];
    float s  = v.x + v.y + v.z + v.w;
    float s2 = v.x*v.x + v.y*v.y + v.z*v.z + v.w*v.w;
    #pragma unroll
    for (int off = 16; off > 0; off >>= 1) {
        s  += __shfl_xor_sync(0xffffffff, s,  off);
        s2 += __shfl_xor_sync(0xffffffff, s2, off);
    }
    if ((tid & 31) == 0) { rs[tid >> 5] = s; rs2[tid >> 5] = s2; }
    __syncthreads();
    if (tid < 8) {
        s = rs[tid]; s2 = rs2[tid];
        #pragma unroll
        for (int off = 4; off > 0; off >>= 1) {
            s  += __shfl_xor_sync(0xff, s,  off);
            s2 += __shfl_xor_sync(0xff, s2, off);
        }
        if (tid == 0) { rs[0] = s; rs2[0] = s2; }
    }
    __syncthreads();
    float mean = rs[0] * (1.0f / NC);
    float var  = rs2[0] * (1.0f / NC) - mean * mean;
    float rstd = rsqrtf(var + LN_EPS);
    const float4* g4 = (const float4*)gg;
    const float4* b4 = (const float4*)bb;
    float4 g = g4[tid], bv = b4[tid];
    float o0 = (v.x - mean) * rstd * g.x + bv.x;
    float o1 = (v.y - mean) * rstd * g.y + bv.y;
    float o2 = (v.z - mean) * rstd * g.z + bv.z;
    float o3 = (v.w - mean) * rstd * g.w + bv.w;
    bf16 h0,l0,h1,l1,h2,l2,h3,l3;
    split2(o0,h0,l0); split2(o1,h1,l1); split2(o2,h2,l2); split2(o3,h3,l3);
    bf162* oh2 = (bf162*)(oh + (long)row * NC);
    bf162* ol2 = (bf162*)(ol + (long)row * NC);
    oh2[tid*2]   = bf162(h0, h1);
    oh2[tid*2+1] = bf162(h2, h3);
    ol2[tid*2]   = bf162(l0, l1);
    ol2[tid*2+1] = bf162(l2, l3);
}

// ---------------- mma.sync helpers ----------------
__device__ __forceinline__ void ldsm_x4(uint32_t addr, uint32_t& r0, uint32_t& r1,
                                        uint32_t& r2, uint32_t& r3) {
    asm volatile("ldmatrix.sync.aligned.m8n8.x4.shared.b16 {%0,%1,%2,%3},[%4];"
                 : "=r"(r0), "=r"(r1), "=r"(r2), "=r"(r3) : "r"(addr));
}
__device__ __forceinline__ void ldsm_x4_t(uint32_t addr, uint32_t& r0, uint32_t& r1,
                                          uint32_t& r2, uint32_t& r3) {
    asm volatile("ldmatrix.sync.aligned.m8n8.x4.trans.shared.b16 {%0,%1,%2,%3},[%4];"
                 : "=r"(r0), "=r"(r1), "=r"(r2), "=r"(r3) : "r"(addr));
}
__device__ __forceinline__ void mma_bf16(float* c, const uint32_t* a, const uint32_t* b) {
    asm volatile(
        "mma.sync.aligned.m16n8k16.row.col.f32.bf16.bf16.f32 "
        "{%0,%1,%2,%3},{%4,%5,%6,%7},{%8,%9},{%0,%1,%2,%3};"
        : "+f"(c[0]), "+f"(c[1]), "+f"(c[2]), "+f"(c[3])
        : "r"(a[0]), "r"(a[1]), "r"(a[2]), "r"(a[3]), "r"(b[0]), "r"(b[1]));
}
__device__ __forceinline__ void cpa16(uint32_t s, const void* g) {
    asm volatile("cp.async.cg.shared.global [%0],[%1],16;" :: "r"(s), "l"(g));
}

// ---------------- split-bf16 tensor-core GEMM, 3-stage pipeline ----------------
// C(BMxN tile) = Ah@Bh + Al@Bh + Ah@Bl, fp32 accum.
// IM=2 -> BM=128 (warp tile 32x64), IM=1 -> BM=64 (warp tile 16x64). BN=128, BK=32.
// stage = A(hi+lo) 2*BM*64B + B(hi+lo) 16KB; 3 stages.
// EPI: 0 = fp32 out; 1 = +bias +res fp32 out; 2 = +bias relu split bf16 out.
#define SMEM_G128 (3*32768)
#define SMEM_G64  (3*24576)

template<int EPI, int IM>
__global__ __launch_bounds__(256, 2)
void mma_gemm(int M, int N, int K,
              const bf16* __restrict__ Ah, const bf16* __restrict__ Al,
              const bf16* __restrict__ Bh, const bf16* __restrict__ Bl,
              const float* __restrict__ bias, const float* __restrict__ res,
              float* __restrict__ Cf, bf16* __restrict__ Ch, bf16* __restrict__ Cl) {
    const int BM = 64 * IM;
    const int ABYTES = BM * 64;                 // one A operand (hi or lo) per stage
    const int STG = 2 * ABYTES + 16384;         // stage bytes
    extern __shared__ char smem[];
    const uint32_t sbase0 = (uint32_t)__cvta_generic_to_shared(smem);
    const int tid  = threadIdx.x;
    const int lane = tid & 31, warp = tid >> 5;
    const int wm = warp >> 1, wn = warp & 1;        // 4 x 2 warps
    const int m0 = blockIdx.y * BM, n0 = blockIdx.x * 128;
    const int r8 = lane & 7, grp = lane >> 3;
    const int g = lane >> 2, t4 = lane & 3;

    float acc[IM][8][4];
    #pragma unroll
    for (int i = 0; i < IM; i++)
        #pragma unroll
        for (int j = 0; j < 8; j++)
            #pragma unroll
            for (int r = 0; r < 4; r++) acc[i][j][r] = 0.f;

    const int T = K >> 5;

    auto load_stage = [&](int stage, int k0) {
        uint32_t sb = sbase0 + stage * STG;
        #pragma unroll
        for (int it = 0; it < IM; it++) {
            int c = it * 256 + tid;          // 0..BM*4-1
            int r = c >> 2, cc = c & 3;      // 4 x 16B chunks per 64B row
            uint32_t so = r * 64 + ((cc ^ ((r >> 1) & 3)) << 4);
            size_t ga = (size_t)(m0 + r) * K + k0 + (cc << 3);
            cpa16(sb +          so, Ah + ga);
            cpa16(sb + ABYTES + so, Al + ga);
        }
        #pragma unroll
        for (int it = 0; it < 2; it++) {
            int c = it * 256 + tid;          // 0..511
            int k = c >> 4, nc = c & 15;     // 16 x 16B chunks per 256B row
            uint32_t so = k * 256 + ((nc ^ (k & 7)) << 4);
            size_t ga = (size_t)(k0 + k) * N + n0 + (nc << 3);
            cpa16(sb + 2*ABYTES +        so, Bh + ga);
            cpa16(sb + 2*ABYTES + 8192 + so, Bl + ga);
        }
    };

    load_stage(0, 0);
    asm volatile("cp.async.commit_group;");
    load_stage(1, 32);
    asm volatile("cp.async.commit_group;");

    for (int t = 0; t < T; t++) {
        if (t + 1 < T) asm volatile("cp.async.wait_group 1;");
        else           asm volatile("cp.async.wait_group 0;");
        __syncthreads();

        int st = t % 3;
        uint32_t sA  = sbase0 + st * STG;
        uint32_t sAl = sA + ABYTES;
        uint32_t sB  = sA + 2*ABYTES;
        uint32_t sBl = sB + 8192;

        #pragma unroll
        for (int kt = 0; kt < 2; kt++) {
            uint32_t ah[IM][4], al_[IM][4];
            #pragma unroll
            for (int i = 0; i < IM; i++) {
                int row = wm * (16*IM) + i * 16 + r8 + ((grp & 1) << 3);
                int kc  = kt * 2 + (grp >> 1);
                uint32_t off = row * 64 + ((kc ^ ((row >> 1) & 3)) << 4);
                ldsm_x4(sA  + off, ah[i][0],  ah[i][1],  ah[i][2],  ah[i][3]);
                ldsm_x4(sAl + off, al_[i][0], al_[i][1], al_[i][2], al_[i][3]);
            }
            #pragma unroll
            for (int half = 0; half < 2; half++) {
                uint32_t bh[4][2], bl_[4][2];
                #pragma unroll
                for (int j4 = 0; j4 < 2; j4++) {
                    int k = kt * 16 + r8 + ((grp & 1) << 3);
                    int nch = wn * 8 + (half * 2 + j4) * 2 + (grp >> 1);
                    uint32_t off = k * 256 + ((nch ^ (k & 7)) << 4);
                    ldsm_x4_t(sB  + off, bh[2*j4][0],  bh[2*j4][1],  bh[2*j4+1][0],  bh[2*j4+1][1]);
                    ldsm_x4_t(sBl + off, bl_[2*j4][0], bl_[2*j4][1], bl_[2*j4+1][0], bl_[2*j4+1][1]);
                }
                #pragma unroll
                for (int i = 0; i < IM; i++)
                    #pragma unroll
                    for (int jl = 0; jl < 4; jl++) {
                        float* a = acc[i][half * 4 + jl];
                        mma_bf16(a, ah[i],  bh[jl]);
                        mma_bf16(a, al_[i], bh[jl]);
                        mma_bf16(a, ah[i],  bl_[jl]);
                    }
            }
        }
        __syncthreads();
        if (t + 2 < T) {
            load_stage((t + 2) % 3, (t + 2) << 5);
            asm volatile("cp.async.commit_group;");
        }
    }

    #pragma unroll
    for (int i = 0; i < IM; i++) {
        int ra = m0 + wm * (16*IM) + i * 16 + g;
        int rb = ra + 8;
        #pragma unroll
        for (int j = 0; j < 8; j++) {
            int c = n0 + wn * 64 + j * 8 + t4 * 2;
            float v0 = acc[i][j][0], v1 = acc[i][j][1];
            float v2 = acc[i][j][2], v3 = acc[i][j][3];
            if (EPI >= 1) {
                float b0 = bias[c], b1 = bias[c + 1];
                v0 += b0; v1 += b1; v2 += b0; v3 += b1;
            }
            if (EPI == 1) {
                const float2 ra2 = *(const float2*)(res + (size_t)ra * N + c);
                const float2 rb2 = *(const float2*)(res + (size_t)rb * N + c);
                v0 += ra2.x; v1 += ra2.y; v2 += rb2.x; v3 += rb2.y;
            }
            if (EPI <= 1) {
                *(float2*)(Cf + (size_t)ra * N + c) = make_float2(v0, v1);
                *(float2*)(Cf + (size_t)rb * N + c) = make_float2(v2, v3);
            } else {
                v0 = fmaxf(v0, 0.f); v1 = fmaxf(v1, 0.f);
                v2 = fmaxf(v2, 0.f); v3 = fmaxf(v3, 0.f);
                bf16 h0,l0,h1,l1,h2,l2,h3,l3;
                split2(v0,h0,l0); split2(v1,h1,l1);
                split2(v2,h2,l2); split2(v3,h3,l3);
                *(bf162*)(Ch + (size_t)ra * N + c) = bf162(h0, h1);
                *(bf162*)(Ch + (size_t)rb * N + c) = bf162(h2, h3);
                *(bf162*)(Cl + (size_t)ra * N + c) = bf162(l0, l1);
                *(bf162*)(Cl + (size_t)rb * N + c) = bf162(l2, l3);
            }
        }
    }
}

// ---------------- flash attention: block = (b, h, 64-query tile) ----------------
#define AQ_PAD 65
#define AV_PAD 68
#define A_QS 0
#define A_KS (64*AQ_PAD)
#define A_VS (A_KS + 64*AQ_PAD)
#define A_PS (A_VS + 64*AV_PAD)
#define A_ST (A_PS + 64*AQ_PAD)
#define SMEM_ATTN ((A_ST + 3*64) * 4)

__global__ __launch_bounds__(256, 2)
void attn_kernel(const float* __restrict__ QKV,
                 bf16* __restrict__ Yh, bf16* __restrict__ Yl) {
    extern __shared__ float sm[];
    float* Qs = sm + A_QS;          // [d][q]
    float* Ks = sm + A_KS;          // [d][s]
    float* Vs = sm + A_VS;          // [s][d]
    float* Ps = sm + A_PS;          // [q][s]
    float* smM = sm + A_ST;
    float* smL = smM + 64;
    float* smC = smL + 64;

    const int qt = (int)(gridDim.x - 1 - blockIdx.x);   // heavy tiles first
    const int h = blockIdx.y, b = blockIdx.z;
    const int tid = threadIdx.x;
    const int qx = tid >> 4, kx = tid & 15;
    const long baseQ = (long)(b * NT) * C3 + h * HDIM;
    const long baseK = baseQ + NC;
    const long baseV = baseQ + 2 * NC;
    const int q0 = qt * 64;

    #pragma unroll
    for (int it = 0; it < 4; it++) {
        int i = it * 256 + tid;
        int r = i >> 4, dc = (i & 15) * 4;
        float4 v = *(const float4*)&QKV[baseQ + (long)(q0 + r) * C3 + dc];
        Qs[(dc+0)*AQ_PAD + r] = v.x; Qs[(dc+1)*AQ_PAD + r] = v.y;
        Qs[(dc+2)*AQ_PAD + r] = v.z; Qs[(dc+3)*AQ_PAD + r] = v.w;
    }
    if (tid < 64) { smM[tid] = -1e30f; smL[tid] = 0.f; }

    float O[4][4];
    #pragma unroll
    for (int i = 0; i < 4; i++)
        #pragma unroll
        for (int j = 0; j < 4; j++) O[i][j] = 0.f;
    __syncthreads();

    for (int jt = 0; jt <= qt; jt++) {
        #pragma unroll
        for (int it = 0; it < 4; it++) {
            int i = it * 256 + tid;
            int r = i >> 4, dc = (i & 15) * 4;
            float4 v = *(const float4*)&QKV[baseK + (long)(jt * 64 + r) * C3 + dc];
            Ks[(dc+0)*AQ_PAD + r] = v.x; Ks[(dc+1)*AQ_PAD + r] = v.y;
            Ks[(dc+2)*AQ_PAD + r] = v.z; Ks[(dc+3)*AQ_PAD + r] = v.w;
            float4 w = *(const float4*)&QKV[baseV + (long)(jt * 64 + r) * C3 + dc];
            *(float4*)&Vs[r * AV_PAD + dc] = w;
        }
        __syncthreads();

        float S[4][4];
        #pragma unroll
        for (int i = 0; i < 4; i++)
            #pragma unroll
            for (int j = 0; j < 4; j++) S[i][j] = 0.f;
        #pragma unroll 4
        for (int d = 0; d < 64; d++) {
            float qm[4], kn[4];
            #pragma unroll
            for (int i = 0; i < 4; i++) qm[i] = Qs[d*AQ_PAD + qx*4 + i];
            #pragma unroll
            for (int j = 0; j < 4; j++) kn[j] = Ks[d*AQ_PAD + kx*4 + j];
            #pragma unroll
            for (int i = 0; i < 4; i++)
                #pragma unroll
                for (int j = 0; j < 4; j++) S[i][j] += qm[i] * kn[j];
        }
        const bool diag = (jt == qt);
        #pragma unroll
        for (int i = 0; i < 4; i++)
            #pragma unroll
            for (int j = 0; j < 4; j++) {
                float s = S[i][j] * 0.125f;
                if (diag && (jt*64 + kx*4 + j > q0 + qx*4 + i)) s = -1e30f;
                Ps[(qx*4+i)*AQ_PAD + kx*4 + j] = s;
            }
        __syncthreads();

        if (tid < 64) {
            float mo = smM[tid], rmax = mo;
            #pragma unroll 8
            for (int s = 0; s < 64; s++) rmax = fmaxf(rmax, Ps[tid*AQ_PAD + s]);
            float c = __expf(mo - rmax);
            float rs = 0.f;
            #pragma unroll 8
            for (int s = 0; s < 64; s++) {
                float p = __expf(Ps[tid*AQ_PAD + s] - rmax);
                Ps[tid*AQ_PAD + s] = p;
                rs += p;
            }
            smL[tid] = smL[tid] * c + rs;
            smM[tid] = rmax;
            smC[tid] = c;
        }
        __syncthreads();

        float cq[4];
        #pragma unroll
        for (int i = 0; i < 4; i++) cq[i] = smC[qx*4 + i];
        #pragma unroll
        for (int i = 0; i < 4; i++)
            #pragma unroll
            for (int j = 0; j < 4; j++) O[i][j] *= cq[i];
        #pragma unroll 4
        for (int s = 0; s < 64; s++) {
            float pv[4], vv[4];
            #pragma unroll
            for (int i = 0; i < 4; i++) pv[i] = Ps[(qx*4+i)*AQ_PAD + s];
            #pragma unroll
            for (int j = 0; j < 4; j++) vv[j] = Vs[s*AV_PAD + kx*4 + j];
            #pragma unroll
            for (int i = 0; i < 4; i++)
                #pragma unroll
                for (int j = 0; j < 4; j++) O[i][j] += pv[i] * vv[j];
        }
        __syncthreads();
    }

    #pragma unroll
    for (int i = 0; i < 4; i++) {
        float inv = 1.0f / smL[qx*4 + i];
        long row = (long)(b * NT + q0 + qx*4 + i);
        long o = row * NC + h * HDIM + kx*4;
        #pragma unroll
        for (int j = 0; j < 4; j += 2) {
            float v0 = O[i][j] * inv, v1 = O[i][j+1] * inv;
            bf16 h0, l0, h1, l1;
            split2(v0, h0, l0); split2(v1, h1, l1);
            *(bf162*)(Yh + o + j) = bf162(h0, h1);
            *(bf162*)(Yl + o + j) = bf162(l0, l1);
        }
    }
}

// ---------------- host driver ----------------
extern "C" void kernel_launch(void* const* d_in, const int* in_sizes, int n_in,
                              void* d_out, int out_size) {
    const int*   idx  = (const int*)  d_in[0];
    const float* tok  = (const float*)d_in[1];
    const float* pos  = (const float*)d_in[2];
    const float* wq   = (const float*)d_in[3];
    const float* wk   = (const float*)d_in[4];
    const float* wv   = (const float*)d_in[5];
    const float* wo   = (const float*)d_in[6];
    const float* bo   = (const float*)d_in[7];
    const float* ln1g = (const float*)d_in[8];
    const float* ln1b = (const float*)d_in[9];
    const float* ln2g = (const float*)d_in[10];
    const float* ln2b = (const float*)d_in[11];
    const float* w1   = (const float*)d_in[12];
    const float* b1   = (const float*)d_in[13];
    const float* w2   = (const float*)d_in[14];
    const float* b2   = (const float*)d_in[15];
    const float* lnfg = (const float*)d_in[16];
    const float* lnfb = (const float*)d_in[17];
    const float* wlm  = (const float*)d_in[18];
    float* out = (float*)d_out;

    static bool attr_done = false;
    if (!attr_done) {
        cudaFuncSetAttribute(mma_gemm<0,2>, cudaFuncAttributeMaxDynamicSharedMemorySize, SMEM_G128);
        cudaFuncSetAttribute(mma_gemm<1,1>, cudaFuncAttributeMaxDynamicSharedMemorySize, SMEM_G64);
        cudaFuncSetAttribute(mma_gemm<2,2>, cudaFuncAttributeMaxDynamicSharedMemorySize, SMEM_G128);
        cudaFuncSetAttribute(attn_kernel, cudaFuncAttributeMaxDynamicSharedMemorySize, SMEM_ATTN);
        attr_done = true;
    }

    float *x, *qkv;
    bf16 *xnh, *xnl, *yh, *yl, *hh, *hl;
    bf16 *wqkvh, *wqkvl, *woh, *wol, *w1h, *w1l, *w2h, *w2l, *lmh, *lml;
    cudaGetSymbolAddress((void**)&x,     g_x);
    cudaGetSymbolAddress((void**)&qkv,   g_qkv);
    cudaGetSymbolAddress((void**)&xnh,   g_xn_h);
    cudaGetSymbolAddress((void**)&xnl,   g_xn_l);
    cudaGetSymbolAddress((void**)&yh,    g_y_h);
    cudaGetSymbolAddress((void**)&yl,    g_y_l);
    cudaGetSymbolAddress((void**)&hh,    g_h_h);
    cudaGetSymbolAddress((void**)&hl,    g_h_l);
    cudaGetSymbolAddress((void**)&wqkvh, g_wqkv_h);
    cudaGetSymbolAddress((void**)&wqkvl, g_wqkv_l);
    cudaGetSymbolAddress((void**)&woh,   g_wo_h);
    cudaGetSymbolAddress((void**)&wol,   g_wo_l);
    cudaGetSymbolAddress((void**)&w1h,   g_w1_h);
    cudaGetSymbolAddress((void**)&w1l,   g_w1_l);
    cudaGetSymbolAddress((void**)&w2h,   g_w2_h);
    cudaGetSymbolAddress((void**)&w2l,   g_w2_l);
    cudaGetSymbolAddress((void**)&lmh,   g_lm_h);
    cudaGetSymbolAddress((void**)&lml,   g_lm_l);

    pack_qkv_kernel<<<4096, 256>>>(wq, wk, wv, wqkvh, wqkvl, (long)NL*NC*C3);
    split4_kernel<<<8192, 256>>>(wo,  woh, wol, (long)NL*NC*NC,
                                 w1,  w1h, w1l, (long)NL*NC*NF,
                                 w2,  w2h, w2l, (long)NL*NF*NC,
                                 wlm, lmh, lml, (long)NC*NV);
    embed_kernel<<<MROWS, 256>>>(idx, tok, pos);

    for (int l = 0; l < NL; l++) {
        const long oQ = (long)l * NC * C3;
        const long oO = (long)l * NC * NC;
        const long o1 = (long)l * NC * NF;
        const long o2 = (long)l * NF * NC;

        ln_split_kernel<<<MROWS, 256>>>(x, ln1g + l*NC, ln1b + l*NC, xnh, xnl);
        mma_gemm<0,2><<<dim3(C3/128, MROWS/128), 256, SMEM_G128>>>(
            MROWS, C3, NC, xnh, xnl, wqkvh + oQ, wqkvl + oQ,
            nullptr, nullptr, qkv, nullptr, nullptr);
        attn_kernel<<<dim3(NT/64, NH, NB), 256, SMEM_ATTN>>>(qkv, yh, yl);
        mma_gemm<1,1><<<dim3(NC/128, MROWS/64), 256, SMEM_G64>>>(
            MROWS, NC, NC, yh, yl, woh + oO, wol + oO,
            bo + l*NC, x, x, nullptr, nullptr);
        ln_split_kernel<<<MROWS, 256>>>(x, ln2g + l*NC, ln2b + l*NC, xnh, xnl);
        mma_gemm<2,2><<<dim3(NF/128, MROWS/128), 256, SMEM_G128>>>(
            MROWS, NF, NC, xnh, xnl, w1h + o1, w1l + o1,
            b1 + l*NF, nullptr, nullptr, hh, hl);
        mma_gemm<1,1><<<dim3(NC/128, MROWS/64), 256, SMEM_G64>>>(
            MROWS, NC, NF, hh, hl, w2h + o2, w2l + o2,
            b2 + l*NC, x, x, nullptr, nullptr);
    }

    ln_split_kernel<<<MROWS, 256>>>(x, lnfg, lnfb, xnh, xnl);
    mma_gemm<0,2><<<dim3(NV/128, MROWS/128), 256, SMEM_G128>>>(
        MROWS, NV, NC, xnh, xnl, lmh, lml,
        nullptr, nullptr, out, nullptr, nullptr);
}

// round 10
// speedup vs baseline: 1.0443x; 1.0443x over previous
#include <cuda_runtime.h>
#include <cuda_bf16.h>
#include <math.h>
#include <stdint.h>

#define NL 12
#define NH 16
#define NC 1024
#define NT 512
#define NB 4
#define HDIM 64
#define NF 4096
#define NV 32000
#define MROWS (NB*NT)   // 2048
#define C3 (3*NC)       // 3072
#define LN_EPS 1e-5f

typedef __nv_bfloat16 bf16;
typedef __nv_bfloat162 bf162;

// ---------------- static scratch ----------------
__device__ float g_x   [MROWS*NC];
__device__ float g_qkv [MROWS*C3];
__device__ bf16  g_xn_h[MROWS*NC];
__device__ bf16  g_xn_l[MROWS*NC];
__device__ bf16  g_y_h [MROWS*NC];
__device__ bf16  g_y_l [MROWS*NC];
__device__ bf16  g_h_h [MROWS*NF];
__device__ bf16  g_h_l [MROWS*NF];

// split weights, K-major W[K,N] (as in reference)
__device__ bf16 g_wqkv_h[(long)NL*NC*C3];
__device__ bf16 g_wqkv_l[(long)NL*NC*C3];
__device__ bf16 g_wo_h  [(long)NL*NC*NC];
__device__ bf16 g_wo_l  [(long)NL*NC*NC];
__device__ bf16 g_w1_h  [(long)NL*NC*NF];
__device__ bf16 g_w1_l  [(long)NL*NC*NF];
__device__ bf16 g_w2_h  [(long)NL*NF*NC];
__device__ bf16 g_w2_l  [(long)NL*NF*NC];
__device__ bf16 g_lm_h  [(long)NC*NV];
__device__ bf16 g_lm_l  [(long)NC*NV];

__device__ __forceinline__ void split2(float v, bf16& h, bf16& l) {
    h = __float2bfloat16(v);
    l = __float2bfloat16(v - __bfloat162float(h));
}

// ---------------- conversion kernels ----------------
__global__ void split4_kernel(const float* __restrict__ i0, bf16* __restrict__ h0, bf16* __restrict__ l0, long n0,
                              const float* __restrict__ i1, bf16* __restrict__ h1, bf16* __restrict__ l1, long n1,
                              const float* __restrict__ i2, bf16* __restrict__ h2, bf16* __restrict__ l2, long n2,
                              const float* __restrict__ i3, bf16* __restrict__ h3, bf16* __restrict__ l3, long n3) {
    long total = n0 + n1 + n2 + n3;
    for (long i = (long)blockIdx.x * blockDim.x + threadIdx.x; i < total;
         i += (long)gridDim.x * blockDim.x) {
        const float* in; bf16 *oh, *ol; long j = i;
        if (j < n0)                { in = i0; oh = h0; ol = l0; }
        else if ((j -= n0) < n1)   { in = i1; oh = h1; ol = l1; }
        else if ((j -= n1) < n2)   { in = i2; oh = h2; ol = l2; }
        else { j -= n2;              in = i3; oh = h3; ol = l3; }
        float v = in[j];
        bf16 h, l; split2(v, h, l);
        oh[j] = h; ol[j] = l;
    }
}

__global__ void pack_qkv_kernel(const float* __restrict__ wq,
                                const float* __restrict__ wk,
                                const float* __restrict__ wv,
                                bf16* __restrict__ oh, bf16* __restrict__ ol, long n) {
    for (long i = (long)blockIdx.x * blockDim.x + threadIdx.x; i < n;
         i += (long)gridDim.x * blockDim.x) {
        long lk = i / C3;        // l*NC + k
        int  j  = (int)(i % C3);
        int sel = j >> 10, jj = j & 1023;
        const float* src = (sel == 0) ? wq : (sel == 1) ? wk : wv;
        float v = src[lk * NC + jj];
        bf16 h, l; split2(v, h, l);
        oh[i] = h; ol[i] = l;
    }
}

// ---------------- embedding ----------------
__global__ void embed_kernel(const int* __restrict__ idx,
                             const float* __restrict__ tok,
                             const float* __restrict__ pos) {
    int row = blockIdx.x, t = row % NT;
    int tk = idx[row];
    const float4* tr = (const float4*)(tok + (long)tk * NC);
    const float4* pr = (const float4*)(pos + (long)t  * NC);
    float4* xr = (float4*)(g_x + (long)row * NC);
    for (int c = threadIdx.x; c < NC / 4; c += blockDim.x) {
        float4 a = tr[c], b = pr[c];
        a.x += b.x; a.y += b.y; a.z += b.z; a.w += b.w;
        xr[c] = a;
    }
}

// ---------------- layernorm + split (256 thr/row) ----------------
__global__ __launch_bounds__(256)
void ln_split_kernel(const float* __restrict__ x,
                     const float* __restrict__ gg,
                     const float* __restrict__ bb,
                     bf16* __restrict__ oh, bf16* __restrict__ ol) {
    __shared__ float rs[8], rs2[8];
    const int row = blockIdx.x, tid = threadIdx.x;
    const float4* xr = (const float4*)(x + (long)row * NC);
    float4 v = xr[tid];
    float s  = v.x + v.y + v.z + v.w;
    float s2 = v.x*v.x + v.y*v.y + v.z*v.z + v.w*v.w;
    #pragma unroll
    for (int off = 16; off > 0; off >>= 1) {
        s  += __shfl_xor_sync(0xffffffff, s,  off);
        s2 += __shfl_xor_sync(0xffffffff, s2, off);
    }
    if ((tid & 31) == 0) { rs[tid >> 5] = s; rs2[tid >> 5] = s2; }
    __syncthreads();
    if (tid < 8) {
        s = rs[tid]; s2 = rs2[tid];
        #pragma unroll
        for (int off = 4; off > 0; off >>= 1) {
            s  += __shfl_xor_sync(0xff, s,  off);
            s2 += __shfl_xor_sync(0xff, s2, off);
        }
        if (tid == 0) { rs[0] = s; rs2[0] = s2; }
    }
    __syncthreads();
    float mean = rs[0] * (1.0f / NC);
    float var  = rs2[0] * (1.0f / NC) - mean * mean;
    float rstd = rsqrtf(var + LN_EPS);
    const float4* g4 = (const float4*)gg;
    const float4* b4 = (const float4*)bb;
    float4 g = g4[tid], bv = b4[tid];
    float o0 = (v.x - mean) * rstd * g.x + bv.x;
    float o1 = (v.y - mean) * rstd * g.y + bv.y;
    float o2 = (v.z - mean) * rstd * g.z + bv.z;
    float o3 = (v.w - mean) * rstd * g.w + bv.w;
    bf16 h0,l0,h1,l1,h2,l2,h3,l3;
    split2(o0,h0,l0); split2(o1,h1,l1); split2(o2,h2,l2); split2(o3,h3,l3);
    bf162* oh2 = (bf162*)(oh + (long)row * NC);
    bf162* ol2 = (bf162*)(ol + (long)row * NC);
    oh2[tid*2]   = bf162(h0, h1);
    oh2[tid*2+1] = bf162(h2, h3);
    ol2[tid*2]   = bf162(l0, l1);
    ol2[tid*2+1] = bf162(l2, l3);
}

// ---------------- mma.sync helpers ----------------
__device__ __forceinline__ void ldsm_x4(uint32_t addr, uint32_t& r0, uint32_t& r1,
                                        uint32_t& r2, uint32_t& r3) {
    asm volatile("ldmatrix.sync.aligned.m8n8.x4.shared.b16 {%0,%1,%2,%3},[%4];"
                 : "=r"(r0), "=r"(r1), "=r"(r2), "=r"(r3) : "r"(addr));
}
__device__ __forceinline__ void ldsm_x4_t(uint32_t addr, uint32_t& r0, uint32_t& r1,
                                          uint32_t& r2, uint32_t& r3) {
    asm volatile("ldmatrix.sync.aligned.m8n8.x4.trans.shared.b16 {%0,%1,%2,%3},[%4];"
                 : "=r"(r0), "=r"(r1), "=r"(r2), "=r"(r3) : "r"(addr));
}
__device__ __forceinline__ void mma_bf16(float* c, const uint32_t* a, const uint32_t* b) {
    asm volatile(
        "mma.sync.aligned.m16n8k16.row.col.f32.bf16.bf16.f32 "
        "{%0,%1,%2,%3},{%4,%5,%6,%7},{%8,%9},{%0,%1,%2,%3};"
        : "+f"(c[0]), "+f"(c[1]), "+f"(c[2]), "+f"(c[3])
        : "r"(a[0]), "r"(a[1]), "r"(a[2]), "r"(a[3]), "r"(b[0]), "r"(b[1]));
}
__device__ __forceinline__ void cpa16(uint32_t s, const void* g) {
    asm volatile("cp.async.cg.shared.global [%0],[%1],16;" :: "r"(s), "l"(g));
}

// ---------------- split-bf16 tensor-core GEMM (R7, 2-stage, known-good) ----------------
#define SMEM_GEMM 65536

template<int EPI>
__global__ __launch_bounds__(256, 2)
void mma_gemm(int M, int N, int K,
              const bf16* __restrict__ Ah, const bf16* __restrict__ Al,
              const bf16* __restrict__ Bh, const bf16* __restrict__ Bl,
              const float* __restrict__ bias, const float* __restrict__ res,
              float* __restrict__ Cf, bf16* __restrict__ Ch, bf16* __restrict__ Cl) {
    extern __shared__ char smem[];
    const uint32_t sbase0 = (uint32_t)__cvta_generic_to_shared(smem);
    const int tid  = threadIdx.x;
    const int lane = tid & 31, warp = tid >> 5;
    const int wm = warp >> 1, wn = warp & 1;        // 4 x 2 warps
    const int m0 = blockIdx.y * 128, n0 = blockIdx.x * 128;
    const int r8 = lane & 7, grp = lane >> 3;
    const int g = lane >> 2, t4 = lane & 3;

    float acc[2][8][4];
    #pragma unroll
    for (int i = 0; i < 2; i++)
        #pragma unroll
        for (int j = 0; j < 8; j++)
            #pragma unroll
            for (int r = 0; r < 4; r++) acc[i][j][r] = 0.f;

    const int T = K >> 5;

    auto load_stage = [&](int stage, int k0) {
        uint32_t sb = sbase0 + stage * 32768;
        #pragma unroll
        for (int it = 0; it < 2; it++) {
            int c = it * 256 + tid;
            int r = c >> 2, cc = c & 3;
            uint32_t so = r * 64 + ((cc ^ ((r >> 1) & 3)) << 4);
            size_t ga = (size_t)(m0 + r) * K + k0 + (cc << 3);
            cpa16(sb +        so, Ah + ga);
            cpa16(sb + 8192 + so, Al + ga);
        }
        #pragma unroll
        for (int it = 0; it < 2; it++) {
            int c = it * 256 + tid;
            int k = c >> 4, nc = c & 15;
            uint32_t so = k * 256 + ((nc ^ (k & 7)) << 4);
            size_t ga = (size_t)(k0 + k) * N + n0 + (nc << 3);
            cpa16(sb + 16384 + so, Bh + ga);
            cpa16(sb + 24576 + so, Bl + ga);
        }
    };

    load_stage(0, 0);
    asm volatile("cp.async.commit_group;");

    for (int t = 0; t < T; t++) {
        if (t + 1 < T) {
            load_stage((t + 1) & 1, (t + 1) << 5);
            asm volatile("cp.async.commit_group;");
            asm volatile("cp.async.wait_group 1;");
        } else {
            asm volatile("cp.async.wait_group 0;");
        }
        __syncthreads();

        uint32_t sA  = sbase0 + (t & 1) * 32768;
        uint32_t sAl = sA + 8192;
        uint32_t sB  = sA + 16384;
        uint32_t sBl = sA + 24576;

        #pragma unroll
        for (int kt = 0; kt < 2; kt++) {
            uint32_t ah[2][4], al_[2][4];
            #pragma unroll
            for (int i = 0; i < 2; i++) {
                int row = wm * 32 + i * 16 + r8 + ((grp & 1) << 3);
                int kc  = kt * 2 + (grp >> 1);
                uint32_t off = row * 64 + ((kc ^ ((row >> 1) & 3)) << 4);
                ldsm_x4(sA  + off, ah[i][0],  ah[i][1],  ah[i][2],  ah[i][3]);
                ldsm_x4(sAl + off, al_[i][0], al_[i][1], al_[i][2], al_[i][3]);
            }
            #pragma unroll
            for (int half = 0; half < 2; half++) {
                uint32_t bh[4][2], bl_[4][2];
                #pragma unroll
                for (int j4 = 0; j4 < 2; j4++) {
                    int k = kt * 16 + r8 + ((grp & 1) << 3);
                    int nch = wn * 8 + (half * 2 + j4) * 2 + (grp >> 1);
                    uint32_t off = k * 256 + ((nch ^ (k & 7)) << 4);
                    ldsm_x4_t(sB  + off, bh[2*j4][0],  bh[2*j4][1],  bh[2*j4+1][0],  bh[2*j4+1][1]);
                    ldsm_x4_t(sBl + off, bl_[2*j4][0], bl_[2*j4][1], bl_[2*j4+1][0], bl_[2*j4+1][1]);
                }
                #pragma unroll
                for (int i = 0; i < 2; i++)
                    #pragma unroll
                    for (int jl = 0; jl < 4; jl++) {
                        float* a = acc[i][half * 4 + jl];
                        mma_bf16(a, ah[i],  bh[jl]);
                        mma_bf16(a, al_[i], bh[jl]);
                        mma_bf16(a, ah[i],  bl_[jl]);
                    }
            }
        }
        __syncthreads();
    }

    #pragma unroll
    for (int i = 0; i < 2; i++) {
        int ra = m0 + wm * 32 + i * 16 + g;
        int rb = ra + 8;
        #pragma unroll
        for (int j = 0; j < 8; j++) {
            int c = n0 + wn * 64 + j * 8 + t4 * 2;
            float v0 = acc[i][j][0], v1 = acc[i][j][1];
            float v2 = acc[i][j][2], v3 = acc[i][j][3];
            if (EPI >= 1) {
                float b0 = bias[c], b1 = bias[c + 1];
                v0 += b0; v1 += b1; v2 += b0; v3 += b1;
            }
            if (EPI == 1) {
                const float2 ra2 = *(const float2*)(res + (size_t)ra * N + c);
                const float2 rb2 = *(const float2*)(res + (size_t)rb * N + c);
                v0 += ra2.x; v1 += ra2.y; v2 += rb2.x; v3 += rb2.y;
            }
            if (EPI <= 1) {
                *(float2*)(Cf + (size_t)ra * N + c) = make_float2(v0, v1);
                *(float2*)(Cf + (size_t)rb * N + c) = make_float2(v2, v3);
            } else {
                v0 = fmaxf(v0, 0.f); v1 = fmaxf(v1, 0.f);
                v2 = fmaxf(v2, 0.f); v3 = fmaxf(v3, 0.f);
                bf16 h0,l0,h1,l1,h2,l2,h3,l3;
                split2(v0,h0,l0); split2(v1,h1,l1);
                split2(v2,h2,l2); split2(v3,h3,l3);
                *(bf162*)(Ch + (size_t)ra * N + c) = bf162(h0, h1);
                *(bf162*)(Ch + (size_t)rb * N + c) = bf162(h2, h3);
                *(bf162*)(Cl + (size_t)ra * N + c) = bf162(l0, l1);
                *(bf162*)(Cl + (size_t)rb * N + c) = bf162(l2, l3);
            }
        }
    }
}

// ---------------- tensor-core flash attention ----------------
// block = (b, h, qt of 64 queries), 256 threads = 8 warps as 4(q) x 2(n).
// S = Q K^T and O += P V via mma.sync bf16 3-term split; online softmax in fp32.
// smem bf16 tiles are 64x64, 128B rows, swizzle chunk = ch ^ (row & 7).
#define ATT_QH 0
#define ATT_QL 8192
#define ATT_KH 16384
#define ATT_KL 24576
#define ATT_VH 32768
#define ATT_VL 40960
#define ATT_PH 49152
#define ATT_PL 57344
#define ATT_PS 65536
#define ATT_ST (ATT_PS + 64*65*4)
#define SMEM_ATTN (ATT_ST + 3*64*4)

__global__ __launch_bounds__(256, 2)
void attn_kernel(const float* __restrict__ QKV,
                 bf16* __restrict__ Yh, bf16* __restrict__ Yl) {
    extern __shared__ char smraw[];
    const uint32_t sb = (uint32_t)__cvta_generic_to_shared(smraw);
    float* Ps  = (float*)(smraw + ATT_PS);
    float* smM = (float*)(smraw + ATT_ST);
    float* smL = smM + 64;
    float* smC = smL + 64;

    const int qt = (int)(gridDim.x - 1 - blockIdx.x);   // heavy tiles first
    const int h = blockIdx.y, b = blockIdx.z;
    const int tid = threadIdx.x, lane = tid & 31, warp = tid >> 5;
    const int wq = warp >> 1, ws = warp & 1;
    const int r8 = lane & 7, grp = lane >> 3;
    const int g = lane >> 2, t4 = lane & 3;
    const long baseQ = (long)(b * NT) * C3 + h * HDIM;
    const long baseK = baseQ + NC, baseV = baseQ + 2 * NC;
    const int q0 = qt * 64;

    // load Q tile [q][d] -> split bf16, swizzled
    #pragma unroll
    for (int it = 0; it < 4; it++) {
        int i = it * 256 + tid;
        int r = i >> 4, dc4 = i & 15;
        float4 v = *(const float4*)&QKV[baseQ + (long)(q0 + r) * C3 + dc4 * 4];
        bf16 h0,l0,h1,l1,h2,l2,h3,l3;
        split2(v.x,h0,l0); split2(v.y,h1,l1); split2(v.z,h2,l2); split2(v.w,h3,l3);
        uint32_t off = (uint32_t)(r * 128 + (((dc4 >> 1) ^ (r & 7)) << 4) + (dc4 & 1) * 8);
        union { bf162 b2[2]; uint2 u; } ph, pl;
        ph.b2[0] = bf162(h0, h1); ph.b2[1] = bf162(h2, h3);
        pl.b2[0] = bf162(l0, l1); pl.b2[1] = bf162(l2, l3);
        *(uint2*)(smraw + ATT_QH + off) = ph.u;
        *(uint2*)(smraw + ATT_QL + off) = pl.u;
    }
    if (tid < 64) { smM[tid] = -1e30f; smL[tid] = 0.f; }

    float accO[4][4];
    #pragma unroll
    for (int j = 0; j < 4; j++)
        #pragma unroll
        for (int r = 0; r < 4; r++) accO[j][r] = 0.f;
    __syncthreads();

    for (int jt = 0; jt <= qt; jt++) {
        // load K (transposed to [d][s]) and V ([s][d]) as split bf16
        #pragma unroll
        for (int it = 0; it < 4; it++) {
            int i = it * 256 + tid;
            int r = i >> 4, dc4 = i & 15;
            float4 kv = *(const float4*)&QKV[baseK + (long)(jt * 64 + r) * C3 + dc4 * 4];
            float karr[4] = {kv.x, kv.y, kv.z, kv.w};
            #pragma unroll
            for (int j = 0; j < 4; j++) {
                int d = dc4 * 4 + j;
                bf16 hh, ll; split2(karr[j], hh, ll);
                uint32_t off = (uint32_t)(d * 128 + (((r >> 3) ^ (d & 7)) << 4) + (r & 7) * 2);
                *(bf16*)(smraw + ATT_KH + off) = hh;
                *(bf16*)(smraw + ATT_KL + off) = ll;
            }
            float4 vv = *(const float4*)&QKV[baseV + (long)(jt * 64 + r) * C3 + dc4 * 4];
            bf16 h0,l0,h1,l1,h2,l2,h3,l3;
            split2(vv.x,h0,l0); split2(vv.y,h1,l1); split2(vv.z,h2,l2); split2(vv.w,h3,l3);
            uint32_t off2 = (uint32_t)(r * 128 + (((dc4 >> 1) ^ (r & 7)) << 4) + (dc4 & 1) * 8);
            union { bf162 b2[2]; uint2 u; } ph, pl;
            ph.b2[0] = bf162(h0, h1); ph.b2[1] = bf162(h2, h3);
            pl.b2[0] = bf162(l0, l1); pl.b2[1] = bf162(l2, l3);
            *(uint2*)(smraw + ATT_VH + off2) = ph.u;
            *(uint2*)(smraw + ATT_VL + off2) = pl.u;
        }
        __syncthreads();

        // ---- S = Q K^T (3-term mma), warp tile q16 x s32 ----
        float accS[4][4];
        #pragma unroll
        for (int j = 0; j < 4; j++)
            #pragma unroll
            for (int r = 0; r < 4; r++) accS[j][r] = 0.f;
        #pragma unroll
        for (int kt = 0; kt < 4; kt++) {
            uint32_t qh[4], ql[4];
            int row = wq * 16 + r8 + ((grp & 1) << 3);
            int ch  = kt * 2 + (grp >> 1);
            uint32_t aoff = (uint32_t)(row * 128 + ((ch ^ (row & 7)) << 4));
            ldsm_x4(sb + ATT_QH + aoff, qh[0], qh[1], qh[2], qh[3]);
            ldsm_x4(sb + ATT_QL + aoff, ql[0], ql[1], ql[2], ql[3]);
            uint32_t kh[4][2], kl[4][2];
            #pragma unroll
            for (int j4 = 0; j4 < 2; j4++) {
                int k = kt * 16 + r8 + ((grp & 1) << 3);
                int nch = ws * 4 + j4 * 2 + (grp >> 1);
                uint32_t boff = (uint32_t)(k * 128 + ((nch ^ (k & 7)) << 4));
                ldsm_x4_t(sb + ATT_KH + boff, kh[2*j4][0], kh[2*j4][1], kh[2*j4+1][0], kh[2*j4+1][1]);
                ldsm_x4_t(sb + ATT_KL + boff, kl[2*j4][0], kl[2*j4][1], kl[2*j4+1][0], kl[2*j4+1][1]);
            }
            #pragma unroll
            for (int j = 0; j < 4; j++) {
                mma_bf16(accS[j], qh, kh[j]);
                mma_bf16(accS[j], ql, kh[j]);
                mma_bf16(accS[j], qh, kl[j]);
            }
        }
        // scale + causal mask + store to Ps
        {
            int r0 = wq * 16 + g, r1 = r0 + 8;
            int qg0 = q0 + r0, qg1 = q0 + r1;
            #pragma unroll
            for (int j = 0; j < 4; j++) {
                int colb = ws * 32 + j * 8 + t4 * 2;
                int sg = jt * 64 + colb;
                float v0 = accS[j][0] * 0.125f; if (sg     > qg0) v0 = -1e30f;
                float v1 = accS[j][1] * 0.125f; if (sg + 1 > qg0) v1 = -1e30f;
                float v2 = accS[j][2] * 0.125f; if (sg     > qg1) v2 = -1e30f;
                float v3 = accS[j][3] * 0.125f; if (sg + 1 > qg1) v3 = -1e30f;
                Ps[r0 * 65 + colb]     = v0;
                Ps[r0 * 65 + colb + 1] = v1;
                Ps[r1 * 65 + colb]     = v2;
                Ps[r1 * 65 + colb + 1] = v3;
            }
        }
        __syncthreads();

        // ---- online softmax, one owner thread per query row; write split P ----
        if (tid < 64) {
            float mo = smM[tid], rmax = mo;
            #pragma unroll 8
            for (int s = 0; s < 64; s++) rmax = fmaxf(rmax, Ps[tid * 65 + s]);
            float c = __expf(mo - rmax), rs = 0.f;
            #pragma unroll 8
            for (int s = 0; s < 64; s++) {
                float p = __expf(Ps[tid * 65 + s] - rmax);
                rs += p;
                bf16 hh, ll; split2(p, hh, ll);
                uint32_t off = (uint32_t)(tid * 128 + (((s >> 3) ^ (tid & 7)) << 4) + (s & 7) * 2);
                *(bf16*)(smraw + ATT_PH + off) = hh;
                *(bf16*)(smraw + ATT_PL + off) = ll;
            }
            smL[tid] = smL[tid] * c + rs;
            smM[tid] = rmax;
            smC[tid] = c;
        }
        __syncthreads();

        // ---- O = O*c + P V (3-term mma), warp tile q16 x d32 ----
        {
            float c0 = smC[wq * 16 + g], c1 = smC[wq * 16 + g + 8];
            #pragma unroll
            for (int j = 0; j < 4; j++) {
                accO[j][0] *= c0; accO[j][1] *= c0;
                accO[j][2] *= c1; accO[j][3] *= c1;
            }
        }
        #pragma unroll
        for (int st = 0; st < 4; st++) {
            uint32_t ph[4], pl[4];
            int row = wq * 16 + r8 + ((grp & 1) << 3);
            int ch  = st * 2 + (grp >> 1);
            uint32_t aoff = (uint32_t)(row * 128 + ((ch ^ (row & 7)) << 4));
            ldsm_x4(sb + ATT_PH + aoff, ph[0], ph[1], ph[2], ph[3]);
            ldsm_x4(sb + ATT_PL + aoff, pl[0], pl[1], pl[2], pl[3]);
            uint32_t vh[4][2], vl[4][2];
            #pragma unroll
            for (int j4 = 0; j4 < 2; j4++) {
                int k = st * 16 + r8 + ((grp & 1) << 3);
                int nch = ws * 4 + j4 * 2 + (grp >> 1);
                uint32_t boff = (uint32_t)(k * 128 + ((nch ^ (k & 7)) << 4));
                ldsm_x4_t(sb + ATT_VH + boff, vh[2*j4][0], vh[2*j4][1], vh[2*j4+1][0], vh[2*j4+1][1]);
                ldsm_x4_t(sb + ATT_VL + boff, vl[2*j4][0], vl[2*j4][1], vl[2*j4+1][0], vl[2*j4+1][1]);
            }
            #pragma unroll
            for (int j = 0; j < 4; j++) {
                mma_bf16(accO[j], ph, vh[j]);
                mma_bf16(accO[j], pl, vh[j]);
                mma_bf16(accO[j], ph, vl[j]);
            }
        }
        __syncthreads();
    }

    // write y = O / l, split bf16
    {
        int r0 = wq * 16 + g, r1 = r0 + 8;
        float i0 = 1.0f / smL[r0], i1 = 1.0f / smL[r1];
        #pragma unroll
        for (int j = 0; j < 4; j++) {
            int col = ws * 32 + j * 8 + t4 * 2;
            long ga0 = (long)(b * NT + q0 + r0) * NC + h * HDIM + col;
            long ga1 = (long)(b * NT + q0 + r1) * NC + h * HDIM + col;
            float v0 = accO[j][0] * i0, v1 = accO[j][1] * i0;
            float v2 = accO[j][2] * i1, v3 = accO[j][3] * i1;
            bf16 h0,l0,h1,l1,h2,l2,h3,l3;
            split2(v0,h0,l0); split2(v1,h1,l1); split2(v2,h2,l2); split2(v3,h3,l3);
            *(bf162*)(Yh + ga0) = bf162(h0, h1);
            *(bf162*)(Yl + ga0) = bf162(l0, l1);
            *(bf162*)(Yh + ga1) = bf162(h2, h3);
            *(bf162*)(Yl + ga1) = bf162(l2, l3);
        }
    }
}

// ---------------- host driver ----------------
extern "C" void kernel_launch(void* const* d_in, const int* in_sizes, int n_in,
                              void* d_out, int out_size) {
    const int*   idx  = (const int*)  d_in[0];
    const float* tok  = (const float*)d_in[1];
    const float* pos  = (const float*)d_in[2];
    const float* wq   = (const float*)d_in[3];
    const float* wk   = (const float*)d_in[4];
    const float* wv   = (const float*)d_in[5];
    const float* wo   = (const float*)d_in[6];
    const float* bo   = (const float*)d_in[7];
    const float* ln1g = (const float*)d_in[8];
    const float* ln1b = (const float*)d_in[9];
    const float* ln2g = (const float*)d_in[10];
    const float* ln2b = (const float*)d_in[11];
    const float* w1   = (const float*)d_in[12];
    const float* b1   = (const float*)d_in[13];
    const float* w2   = (const float*)d_in[14];
    const float* b2   = (const float*)d_in[15];
    const float* lnfg = (const float*)d_in[16];
    const float* lnfb = (const float*)d_in[17];
    const float* wlm  = (const float*)d_in[18];
    float* out = (float*)d_out;

    static bool attr_done = false;
    if (!attr_done) {
        cudaFuncSetAttribute(mma_gemm<0>, cudaFuncAttributeMaxDynamicSharedMemorySize, SMEM_GEMM);
        cudaFuncSetAttribute(mma_gemm<1>, cudaFuncAttributeMaxDynamicSharedMemorySize, SMEM_GEMM);
        cudaFuncSetAttribute(mma_gemm<2>, cudaFuncAttributeMaxDynamicSharedMemorySize, SMEM_GEMM);
        cudaFuncSetAttribute(attn_kernel, cudaFuncAttributeMaxDynamicSharedMemorySize, SMEM_ATTN);
        attr_done = true;
    }

    float *x, *qkv;
    bf16 *xnh, *xnl, *yh, *yl, *hh, *hl;
    bf16 *wqkvh, *wqkvl, *woh, *wol, *w1h, *w1l, *w2h, *w2l, *lmh, *lml;
    cudaGetSymbolAddress((void**)&x,     g_x);
    cudaGetSymbolAddress((void**)&qkv,   g_qkv);
    cudaGetSymbolAddress((void**)&xnh,   g_xn_h);
    cudaGetSymbolAddress((void**)&xnl,   g_xn_l);
    cudaGetSymbolAddress((void**)&yh,    g_y_h);
    cudaGetSymbolAddress((void**)&yl,    g_y_l);
    cudaGetSymbolAddress((void**)&hh,    g_h_h);
    cudaGetSymbolAddress((void**)&hl,    g_h_l);
    cudaGetSymbolAddress((void**)&wqkvh, g_wqkv_h);
    cudaGetSymbolAddress((void**)&wqkvl, g_wqkv_l);
    cudaGetSymbolAddress((void**)&woh,   g_wo_h);
    cudaGetSymbolAddress((void**)&wol,   g_wo_l);
    cudaGetSymbolAddress((void**)&w1h,   g_w1_h);
    cudaGetSymbolAddress((void**)&w1l,   g_w1_l);
    cudaGetSymbolAddress((void**)&w2h,   g_w2_h);
    cudaGetSymbolAddress((void**)&w2l,   g_w2_l);
    cudaGetSymbolAddress((void**)&lmh,   g_lm_h);
    cudaGetSymbolAddress((void**)&lml,   g_lm_l);

    pack_qkv_kernel<<<4096, 256>>>(wq, wk, wv, wqkvh, wqkvl, (long)NL*NC*C3);
    split4_kernel<<<8192, 256>>>(wo,  woh, wol, (long)NL*NC*NC,
                                 w1,  w1h, w1l, (long)NL*NC*NF,
                                 w2,  w2h, w2l, (long)NL*NF*NC,
                                 wlm, lmh, lml, (long)NC*NV);
    embed_kernel<<<MROWS, 256>>>(idx, tok, pos);

    for (int l = 0; l < NL; l++) {
        const long oQ = (long)l * NC * C3;
        const long oO = (long)l * NC * NC;
        const long o1 = (long)l * NC * NF;
        const long o2 = (long)l * NF * NC;

        ln_split_kernel<<<MROWS, 256>>>(x, ln1g + l*NC, ln1b + l*NC, xnh, xnl);
        mma_gemm<0><<<dim3(C3/128, MROWS/128), 256, SMEM_GEMM>>>(
            MROWS, C3, NC, xnh, xnl, wqkvh + oQ, wqkvl + oQ,
            nullptr, nullptr, qkv, nullptr, nullptr);
        attn_kernel<<<dim3(NT/64, NH, NB), 256, SMEM_ATTN>>>(qkv, yh, yl);
        mma_gemm<1><<<dim3(NC/128, MROWS/128), 256, SMEM_GEMM>>>(
            MROWS, NC, NC, yh, yl, woh + oO, wol + oO,
            bo + l*NC, x, x, nullptr, nullptr);
        ln_split_kernel<<<MROWS, 256>>>(x, ln2g + l*NC, ln2b + l*NC, xnh, xnl);
        mma_gemm<2><<<dim3(NF/128, MROWS/128), 256, SMEM_GEMM>>>(
            MROWS, NF, NC, xnh, xnl, w1h + o1, w1l + o1,
            b1 + l*NF, nullptr, nullptr, hh, hl);
        mma_gemm<1><<<dim3(NC/128, MROWS/128), 256, SMEM_GEMM>>>(
            MROWS, NC, NF, hh, hl, w2h + o2, w2l + o2,
            b2 + l*NC, x, x, nullptr, nullptr);
    }

    ln_split_kernel<<<MROWS, 256>>>(x, lnfg, lnfb, xnh, xnl);
    mma_gemm<0><<<dim3(NV/128, MROWS/128), 256, SMEM_GEMM>>>(
        MROWS, NV, NC, xnh, xnl, lmh, lml,
        nullptr, nullptr, out, nullptr, nullptr);
}